// round 4
// baseline (speedup 1.0000x reference)
#include <cuda_runtime.h>
#include <cstdint>

// Problem constants
#define BB 4096
#define NN 8192
#define THREADS 512
#define VECW 4
#define ITERS (NN / (THREADS * VECW))   // 4 float4 chunks per thread
#define GRID  456                       // 152 SMs x 3 resident CTAs: one persistent wave

#define TAU_SYN_INV 0.5f
#define TAU_MEM_INV 0.5f
#define V_TH 1.0f
#define V_RESET 0.0f
#define INHIB (-5.0f)

__device__ __forceinline__ void argmax_combine(float& bv, int& bi, float ov, int oi) {
    // first-max tie-break: strictly greater wins; equal -> smaller index wins
    if (ov > bv || (ov == bv && oi < bi)) { bv = ov; bi = oi; }
}

__global__ void __launch_bounds__(THREADS, 3)
lif_lateral_inhibition_kernel(const float* __restrict__ x,
                              const float* __restrict__ v,
                              const float* __restrict__ icur,
                              float* __restrict__ z_out,
                              float* __restrict__ v_out,
                              float* __restrict__ i_out) {
    const int t    = threadIdx.x;
    const int lane = t & 31;
    const int warp = t >> 5;

    __shared__ float sval[THREADS / 32];
    __shared__ int   sidx[THREADS / 32];
    __shared__ float s_best;
    __shared__ int   s_widx;

    const float NEG_INF = __int_as_float(0xff800000u);
    const float4 inhib4 = make_float4(INHIB, INHIB, INHIB, INHIB);

    for (int row = blockIdx.x; row < BB; row += GRID) {
        const size_t base = (size_t)row * NN;

        const float4* __restrict__ x4 = (const float4*)(x    + base);
        const float4* __restrict__ v4 = (const float4*)(v    + base);
        const float4* __restrict__ c4 = (const float4*)(icur + base);
        float4* __restrict__ z4  = (float4*)(z_out + base);
        float4* __restrict__ io4 = (float4*)(i_out + base);
        float4* __restrict__ vo4 = (float4*)(v_out + base);

        float best = NEG_INF;
        int   bidx = 0x7fffffff;

        // ---- phase 1: stream x, v, i -> write i_new, z, v_out(=INHIB prefill);
        //      track row argmax of v_new among spiked elements ----
        #pragma unroll
        for (int k = 0; k < ITERS; k++) {
            const int q = k * THREADS + t;        // float4 index within row
            float4 xv = __ldcs(x4 + q);
            float4 vv = __ldcs(v4 + q);
            float4 cv = __ldcs(c4 + q);

            // overlap the constant v_out fill with the load stream
            __stcs(vo4 + q, inhib4);

            float4 in4, zz4;
            const float* xp = &xv.x;
            const float* vp = &vv.x;
            const float* cp = &cv.x;
            float* ip = &in4.x;
            float* zp = &zz4.x;

            #pragma unroll
            for (int c = 0; c < VECW; c++) {
                float inew = cp[c] + TAU_SYN_INV * (xp[c] - cp[c]);
                float vnew = vp[c] + TAU_MEM_INV * (inew - vp[c]);
                float zc   = (vnew >= V_TH) ? 1.0f : 0.0f;
                ip[c] = inew;
                zp[c] = zc;
                if (zc > 0.0f) {
                    argmax_combine(best, bidx, vnew, q * VECW + c);
                }
            }
            __stcs(io4 + q, in4);
            __stcs(z4 + q, zz4);
        }

        // ---- block argmax reduction (first-max semantics) ----
        #pragma unroll
        for (int off = 16; off > 0; off >>= 1) {
            float ov = __shfl_xor_sync(0xffffffffu, best, off);
            int   oi = __shfl_xor_sync(0xffffffffu, bidx, off);
            argmax_combine(best, bidx, ov, oi);
        }
        if (lane == 0) { sval[warp] = best; sidx[warp] = bidx; }
        __syncthreads();

        if (warp == 0) {
            float bv = (lane < THREADS / 32) ? sval[lane] : NEG_INF;
            int   bi = (lane < THREADS / 32) ? sidx[lane] : 0x7fffffff;
            #pragma unroll
            for (int off = 16; off > 0; off >>= 1) {
                float ov = __shfl_xor_sync(0xffffffffu, bv, off);
                int   oi = __shfl_xor_sync(0xffffffffu, bi, off);
                argmax_combine(bv, bi, ov, oi);
            }
            if (lane == 0) { s_best = bv; s_widx = bi; }
        }
        __syncthreads();

        const bool any_spike = (s_best >= V_TH);

        if (any_spike) {
            // Winner spiked -> v_after(winner) = V_RESET = 0; everyone else
            // already holds INHIB from the prefill. One store fixes the row.
            if (t == 0) {
                v_out[base + s_widx] = V_RESET;
            }
        } else {
            // Rare: no spikes in row -> v_out = v_new (no resets possible).
            // Recompute from L2-hot v (input) and i_out (just written),
            // bit-identical FMA chain; overwrites the INHIB prefill.
            #pragma unroll
            for (int k = 0; k < ITERS; k++) {
                const int q = k * THREADS + t;
                float4 vv = v4[q];
                float4 iv = io4[q];
                float4 out4;
                const float* vp = &vv.x;
                const float* ip = &iv.x;
                float* op = &out4.x;
                #pragma unroll
                for (int c = 0; c < VECW; c++) {
                    op[c] = vp[c] + TAU_MEM_INV * (ip[c] - vp[c]);
                }
                __stcs(vo4 + q, out4);
            }
        }
        // next-iteration writes to sval/s_best are ordered by the two
        // __syncthreads inside the reduction; no extra barrier needed here.
    }
}

extern "C" void kernel_launch(void* const* d_in, const int* in_sizes, int n_in,
                              void* d_out, int out_size) {
    const float* x = (const float*)d_in[0];
    const float* v = (const float*)d_in[1];
    const float* i = (const float*)d_in[2];

    float* out   = (float*)d_out;
    float* z_out = out;                           // [B, N]
    float* v_out = out + (size_t)BB * NN;         // [B, N]
    float* i_out = out + 2 * (size_t)BB * NN;     // [B, N]

    lif_lateral_inhibition_kernel<<<GRID, THREADS>>>(x, v, i, z_out, v_out, i_out);
}

// round 5
// speedup vs baseline: 1.0959x; 1.0959x over previous
#include <cuda_runtime.h>
#include <cstdint>

// Problem constants
#define BB 4096
#define NN 8192
#define THREADS 256
#define VECW 4
#define ITERS (NN / (THREADS * VECW))   // 8 float4 chunks per thread

#define TAU_SYN_INV 0.5f
#define TAU_MEM_INV 0.5f
#define V_TH 1.0f
#define V_RESET 0.0f
#define INHIB (-5.0f)

__device__ __forceinline__ void argmax_combine(float& bv, int& bi, float ov, int oi) {
    // first-max tie-break: strictly greater wins; equal -> smaller index wins
    if (ov > bv || (ov == bv && oi < bi)) { bv = ov; bi = oi; }
}

__global__ void __launch_bounds__(THREADS, 6)
lif_lateral_inhibition_kernel(const float* __restrict__ x,
                              const float* __restrict__ v,
                              const float* __restrict__ icur,
                              float* __restrict__ z_out,
                              float* __restrict__ v_out,
                              float* __restrict__ i_out) {
    const int row  = blockIdx.x;
    const int t    = threadIdx.x;
    const int lane = t & 31;
    const int warp = t >> 5;
    const size_t base = (size_t)row * NN;

    const float4* __restrict__ x4 = (const float4*)(x    + base);
    const float4* __restrict__ v4 = (const float4*)(v    + base);
    const float4* __restrict__ c4 = (const float4*)(icur + base);
    float4* __restrict__ z4  = (float4*)(z_out + base);
    float4* __restrict__ io4 = (float4*)(i_out + base);
    float4* __restrict__ vo4 = (float4*)(v_out + base);

    const float NEG_INF = __int_as_float(0xff800000u);
    const float4 inhib4 = make_float4(INHIB, INHIB, INHIB, INHIB);

    float best = NEG_INF;
    int   bidx = 0x7fffffff;

    // ---- phase 1: stream x, v, i -> write i_new, z, v_out(=INHIB prefill);
    //      track row argmax of v_new among spiked elements ----
    #pragma unroll
    for (int k = 0; k < ITERS; k++) {
        const int q = k * THREADS + t;        // float4 index within row
        float4 xv = __ldcs(x4 + q);
        float4 vv = __ldcs(v4 + q);
        float4 cv = __ldcs(c4 + q);

        // constant v_out fill overlapped with the load stream
        __stcs(vo4 + q, inhib4);

        float4 in4, zz4;
        const float* xp = &xv.x;
        const float* vp = &vv.x;
        const float* cp = &cv.x;
        float* ip = &in4.x;
        float* zp = &zz4.x;

        #pragma unroll
        for (int c = 0; c < VECW; c++) {
            float inew = cp[c] + TAU_SYN_INV * (xp[c] - cp[c]);
            float vnew = vp[c] + TAU_MEM_INV * (inew - vp[c]);
            float zc   = (vnew >= V_TH) ? 1.0f : 0.0f;
            ip[c] = inew;
            zp[c] = zc;
            if (zc > 0.0f) {
                argmax_combine(best, bidx, vnew, q * VECW + c);
            }
        }
        __stcs(io4 + q, in4);
        __stcs(z4 + q, zz4);
    }

    // ---- block argmax reduction (first-max semantics) ----
    #pragma unroll
    for (int off = 16; off > 0; off >>= 1) {
        float ov = __shfl_xor_sync(0xffffffffu, best, off);
        int   oi = __shfl_xor_sync(0xffffffffu, bidx, off);
        argmax_combine(best, bidx, ov, oi);
    }

    __shared__ float sval[THREADS / 32];
    __shared__ int   sidx[THREADS / 32];
    __shared__ float s_best;
    __shared__ int   s_widx;

    if (lane == 0) { sval[warp] = best; sidx[warp] = bidx; }
    __syncthreads();

    if (warp == 0) {
        float bv = (lane < THREADS / 32) ? sval[lane] : NEG_INF;
        int   bi = (lane < THREADS / 32) ? sidx[lane] : 0x7fffffff;
        #pragma unroll
        for (int off = 4; off > 0; off >>= 1) {
            float ov = __shfl_xor_sync(0xffffffffu, bv, off);
            int   oi = __shfl_xor_sync(0xffffffffu, bi, off);
            argmax_combine(bv, bi, ov, oi);
        }
        if (lane == 0) { s_best = bv; s_widx = bi; }
    }
    __syncthreads();

    const bool any_spike = (s_best >= V_TH);

    if (any_spike) {
        // Winner spiked -> v_after(winner) = V_RESET = 0; all other elements
        // already hold INHIB from the prefill. One store fixes the row.
        if (t == 0) {
            v_out[base + s_widx] = V_RESET;
        }
    } else {
        // Rare: no spikes in row -> v_out = v_new (no resets possible).
        // Recompute from L2-hot v (input) and i_out (just written),
        // bit-identical FMA chain; overwrites the INHIB prefill.
        #pragma unroll
        for (int k = 0; k < ITERS; k++) {
            const int q = k * THREADS + t;
            float4 vv = v4[q];
            float4 iv = io4[q];
            float4 out4;
            const float* vp = &vv.x;
            const float* ip = &iv.x;
            float* op = &out4.x;
            #pragma unroll
            for (int c = 0; c < VECW; c++) {
                op[c] = vp[c] + TAU_MEM_INV * (ip[c] - vp[c]);
            }
            __stcs(vo4 + q, out4);
        }
    }
}

extern "C" void kernel_launch(void* const* d_in, const int* in_sizes, int n_in,
                              void* d_out, int out_size) {
    const float* x = (const float*)d_in[0];
    const float* v = (const float*)d_in[1];
    const float* i = (const float*)d_in[2];

    float* out   = (float*)d_out;
    float* z_out = out;                           // [B, N]
    float* v_out = out + (size_t)BB * NN;         // [B, N]
    float* i_out = out + 2 * (size_t)BB * NN;     // [B, N]

    lif_lateral_inhibition_kernel<<<BB, THREADS>>>(x, v, i, z_out, v_out, i_out);
}

// round 6
// speedup vs baseline: 1.1485x; 1.0480x over previous
#include <cuda_runtime.h>
#include <cstdint>

// Problem constants
#define BB 4096
#define NN 8192
#define THREADS 256
#define VECW 4
#define CTAS_PER_ROW 4
#define CHUNK (NN / CTAS_PER_ROW)               // 2048 elements per CTA
#define ITERS (CHUNK / (THREADS * VECW))        // 2 float4 chunks per thread

#define TAU_SYN_INV 0.5f
#define TAU_MEM_INV 0.5f
#define V_TH 1.0f
#define V_RESET 0.0f
#define INHIB (-5.0f)

// Per-row winner slot: (bits(v_new) << 32) | (0xFFFFFFFF - index).
// Zero-initialized at module load; kernel2 resets after consuming, so every
// graph replay sees zeros. v_new >= V_TH = 1.0 for any spike -> high word
// >= 0x3F800000 iff the row spiked. Positive-float bits are order-monotone,
// and ~index makes equal values prefer the smaller index (first-max).
__device__ unsigned long long g_winner[BB];

__device__ __forceinline__ void argmax_combine(float& bv, int& bi, float ov, int oi) {
    if (ov > bv || (ov == bv && oi < bi)) { bv = ov; bi = oi; }
}

// ---------------------------------------------------------------------------
// Kernel 1: barrier-free streaming pass. 4 CTAs per row.
//   writes i_new, z, v_out = INHIB prefill; merges per-warp argmax candidates
//   into g_winner[row] via atomicMax (RED, no return value used).
// ---------------------------------------------------------------------------
__global__ void __launch_bounds__(THREADS, 6)
lif_phase1(const float* __restrict__ x,
           const float* __restrict__ v,
           const float* __restrict__ icur,
           float* __restrict__ z_out,
           float* __restrict__ v_out,
           float* __restrict__ i_out) {
    const int cta     = blockIdx.x;
    const int row     = cta >> 2;          // CTAS_PER_ROW = 4
    const int quarter = cta & 3;
    const int t       = threadIdx.x;
    const int lane    = t & 31;

    const size_t base = (size_t)row * NN + (size_t)quarter * CHUNK;
    const int    goff = quarter * CHUNK;   // index offset within the row

    const float4* __restrict__ x4 = (const float4*)(x    + base);
    const float4* __restrict__ v4 = (const float4*)(v    + base);
    const float4* __restrict__ c4 = (const float4*)(icur + base);
    float4* __restrict__ z4  = (float4*)(z_out + base);
    float4* __restrict__ io4 = (float4*)(i_out + base);
    float4* __restrict__ vo4 = (float4*)(v_out + base);

    const float NEG_INF = __int_as_float(0xff800000u);
    const float4 inhib4 = make_float4(INHIB, INHIB, INHIB, INHIB);

    float best = NEG_INF;
    int   bidx = 0x7fffffff;

    #pragma unroll
    for (int k = 0; k < ITERS; k++) {
        const int q = k * THREADS + t;     // float4 index within this chunk
        float4 xv = __ldcs(x4 + q);
        float4 vv = __ldcs(v4 + q);
        float4 cv = __ldcs(c4 + q);

        __stcs(vo4 + q, inhib4);           // overlapped constant prefill

        float4 in4, zz4;
        const float* xp = &xv.x;
        const float* vp = &vv.x;
        const float* cp = &cv.x;
        float* ip = &in4.x;
        float* zp = &zz4.x;

        #pragma unroll
        for (int c = 0; c < VECW; c++) {
            float inew = cp[c] + TAU_SYN_INV * (xp[c] - cp[c]);
            float vnew = vp[c] + TAU_MEM_INV * (inew - vp[c]);
            float zc   = (vnew >= V_TH) ? 1.0f : 0.0f;
            ip[c] = inew;
            zp[c] = zc;
            if (zc > 0.0f) {
                argmax_combine(best, bidx, vnew, goff + q * VECW + c);
            }
        }
        __stcs(io4 + q, in4);
        __stcs(z4 + q, zz4);
    }

    // warp argmax (first-max semantics), then one RED per warp
    #pragma unroll
    for (int off = 16; off > 0; off >>= 1) {
        float ov = __shfl_xor_sync(0xffffffffu, best, off);
        int   oi = __shfl_xor_sync(0xffffffffu, bidx, off);
        argmax_combine(best, bidx, ov, oi);
    }
    if (lane == 0 && best >= V_TH) {
        unsigned long long packed =
            ((unsigned long long)__float_as_uint(best) << 32) |
            (unsigned long long)(0xFFFFFFFFu - (unsigned)bidx);
        atomicMax(&g_winner[row], packed);   // result unused -> REDG
    }
}

// ---------------------------------------------------------------------------
// Kernel 2: per-row fix-up. Winner spiked -> v_after(winner) = V_RESET = 0;
// everything else already holds INHIB. Rare no-spike row: rewrite with v_new.
// Resets the slot for the next graph replay.
// ---------------------------------------------------------------------------
__global__ void lif_phase2(const float* __restrict__ v,
                           const float* __restrict__ i_out,
                           float* __restrict__ v_out) {
    const int row = blockIdx.x * blockDim.x + threadIdx.x;
    if (row >= BB) return;

    unsigned long long slot = g_winner[row];
    g_winner[row] = 0ULL;                  // reset for next replay

    const unsigned vb = (unsigned)(slot >> 32);
    const size_t base = (size_t)row * NN;

    if (vb >= 0x3F800000u) {               // any spike in row
        const unsigned widx = 0xFFFFFFFFu - (unsigned)slot;
        v_out[base + widx] = V_RESET;
    } else {
        // No spikes: v_out = v_new (no resets, no inhibition). Rare; scalar ok.
        for (int n = 0; n < NN; n++) {
            float vv = v[base + n];
            float iv = i_out[base + n];
            v_out[base + n] = vv + TAU_MEM_INV * (iv - vv);
        }
    }
}

extern "C" void kernel_launch(void* const* d_in, const int* in_sizes, int n_in,
                              void* d_out, int out_size) {
    const float* x = (const float*)d_in[0];
    const float* v = (const float*)d_in[1];
    const float* i = (const float*)d_in[2];

    float* out   = (float*)d_out;
    float* z_out = out;                           // [B, N]
    float* v_out = out + (size_t)BB * NN;         // [B, N]
    float* i_out = out + 2 * (size_t)BB * NN;     // [B, N]

    lif_phase1<<<BB * CTAS_PER_ROW, THREADS>>>(x, v, i, z_out, v_out, i_out);
    lif_phase2<<<BB / 256, 256>>>(v, i_out, v_out);
}